// round 6
// baseline (speedup 1.0000x reference)
#include <cuda_runtime.h>
#include <cstdint>

// Problem constants (from reference_code)
#define N_NODES 500000
#define N_EDGES 8000000

// ---------------- scratch (device globals: allocation-free) ----------------
__device__ __align__(16) float g_hs1 [N_NODES * 8];   // (x@W1)*dinv[src], 16 MB (L2-resident)
__device__ __align__(16) float g_acc1[N_NODES * 8];   // layer-1 scatter accumulator, 16 MB
__device__ __align__(8)  float g_hs2 [N_NODES * 2];   // layer-2 scaled features, 4 MB
__device__               float g_deg [N_NODES];       // degree (incl. self-loop)
__device__               float g_dinv[N_NODES];       // rsqrt(deg)

// ---------------- kernels ----------------

__global__ void k_init_deg() {
    int i = blockIdx.x * blockDim.x + threadIdx.x;
    if (i < N_NODES) g_deg[i] = 1.0f;   // self-loop contributes 1
}

__global__ void k_degree(const int* __restrict__ ei) {
    int i = blockIdx.x * blockDim.x + threadIdx.x;
    if (i < N_EDGES) {
        int d = ei[N_EDGES + i];        // dst row of edge_index [2, E] (int32!)
        atomicAdd(&g_deg[d], 1.0f);
    }
}

// dinv = rsqrt(deg); hs1 = (x @ W1) * dinv; acc1 = 0
__global__ void k_node1(const float* __restrict__ x, const float* __restrict__ W1) {
    int i = blockIdx.x * blockDim.x + threadIdx.x;
    if (i >= N_NODES) return;
    float dv = rsqrtf(g_deg[i]);
    g_dinv[i] = dv;
    float x0 = x[3 * i], x1 = x[3 * i + 1], x2 = x[3 * i + 2];
    float4* h4 = reinterpret_cast<float4*>(&g_hs1[(size_t)i * 8]);
    float4* a4 = reinterpret_cast<float4*>(&g_acc1[(size_t)i * 8]);
    float h[8];
#pragma unroll
    for (int j = 0; j < 8; j++) {
        h[j] = (x0 * __ldg(&W1[j]) + x1 * __ldg(&W1[8 + j]) + x2 * __ldg(&W1[16 + j])) * dv;
    }
    h4[0] = make_float4(h[0], h[1], h[2], h[3]);
    h4[1] = make_float4(h[4], h[5], h[6], h[7]);
    a4[0] = make_float4(0.f, 0.f, 0.f, 0.f);
    a4[1] = make_float4(0.f, 0.f, 0.f, 0.f);
}

// acc1[dst] += hs1[src]   (8 floats via 2x red.global.add.v4.f32)
__global__ void k_edge1(const int* __restrict__ ei) {
    int i = blockIdx.x * blockDim.x + threadIdx.x;
    if (i >= N_EDGES) return;
    int s = ei[i];
    int d = ei[N_EDGES + i];
    const float4* hp = reinterpret_cast<const float4*>(&g_hs1[(size_t)s * 8]);
    float4 v0 = __ldg(hp);
    float4 v1 = __ldg(hp + 1);
    float* ap = &g_acc1[(size_t)d * 8];
    asm volatile("red.global.add.v4.f32 [%0], {%1,%2,%3,%4};"
                 :: "l"(ap), "f"(v0.x), "f"(v0.y), "f"(v0.z), "f"(v0.w) : "memory");
    asm volatile("red.global.add.v4.f32 [%0], {%1,%2,%3,%4};"
                 :: "l"(ap + 4), "f"(v1.x), "f"(v1.y), "f"(v1.z), "f"(v1.w) : "memory");
}

// a = relu(dinv*(acc1 + hs1) + b1);  hs2 = (a @ W2) * dinv;  out = 0
__global__ void k_node2(const float* __restrict__ b1, const float* __restrict__ W2,
                        float* __restrict__ out) {
    int i = blockIdx.x * blockDim.x + threadIdx.x;
    if (i >= N_NODES) return;
    float dv = g_dinv[i];
    const float4* h4 = reinterpret_cast<const float4*>(&g_hs1[(size_t)i * 8]);
    const float4* a4 = reinterpret_cast<const float4*>(&g_acc1[(size_t)i * 8]);
    float4 h0 = h4[0], h1 = h4[1];
    float4 c0 = a4[0], c1 = a4[1];
    float a[8];
    a[0] = dv * (c0.x + h0.x) + __ldg(&b1[0]);
    a[1] = dv * (c0.y + h0.y) + __ldg(&b1[1]);
    a[2] = dv * (c0.z + h0.z) + __ldg(&b1[2]);
    a[3] = dv * (c0.w + h0.w) + __ldg(&b1[3]);
    a[4] = dv * (c1.x + h1.x) + __ldg(&b1[4]);
    a[5] = dv * (c1.y + h1.y) + __ldg(&b1[5]);
    a[6] = dv * (c1.z + h1.z) + __ldg(&b1[6]);
    a[7] = dv * (c1.w + h1.w) + __ldg(&b1[7]);
#pragma unroll
    for (int j = 0; j < 8; j++) a[j] = fmaxf(a[j], 0.0f);
    float o0 = 0.f, o1 = 0.f;
#pragma unroll
    for (int j = 0; j < 8; j++) {
        o0 += a[j] * __ldg(&W2[2 * j]);
        o1 += a[j] * __ldg(&W2[2 * j + 1]);
    }
    reinterpret_cast<float2*>(&g_hs2[(size_t)i * 2])[0] = make_float2(o0 * dv, o1 * dv);
    reinterpret_cast<float2*>(&out[(size_t)i * 2])[0]   = make_float2(0.f, 0.f);
}

// out[dst] += hs2[src]   (2 floats via red.global.add.v2.f32)
__global__ void k_edge2(const int* __restrict__ ei, float* __restrict__ out) {
    int i = blockIdx.x * blockDim.x + threadIdx.x;
    if (i >= N_EDGES) return;
    int s = ei[i];
    int d = ei[N_EDGES + i];
    float2 v = __ldg(reinterpret_cast<const float2*>(&g_hs2[(size_t)s * 2]));
    float* op = &out[(size_t)d * 2];
    asm volatile("red.global.add.v2.f32 [%0], {%1,%2};"
                 :: "l"(op), "f"(v.x), "f"(v.y) : "memory");
}

// out = dinv*(out + hs2) + b2
__global__ void k_fin(const float* __restrict__ b2, float* __restrict__ out) {
    int i = blockIdx.x * blockDim.x + threadIdx.x;
    if (i >= N_NODES) return;
    float dv = g_dinv[i];
    float2* op = reinterpret_cast<float2*>(&out[(size_t)i * 2]);
    float2 acc = op[0];
    const float2 h = reinterpret_cast<const float2*>(&g_hs2[(size_t)i * 2])[0];
    op[0] = make_float2(dv * (acc.x + h.x) + __ldg(&b2[0]),
                        dv * (acc.y + h.y) + __ldg(&b2[1]));
}

// ---------------- launch ----------------
extern "C" void kernel_launch(void* const* d_in, const int* in_sizes, int n_in,
                              void* d_out, int out_size) {
    const float* x  = (const float*)d_in[0];       // [N, 3] f32
    const int*   ei = (const int*)d_in[1];         // [2, E] int32 (JAX x64 disabled)
    const float* W1 = (const float*)d_in[2];       // [3, 8]
    const float* b1 = (const float*)d_in[3];       // [8]
    const float* W2 = (const float*)d_in[4];       // [8, 2]
    const float* b2 = (const float*)d_in[5];       // [2]
    float* out = (float*)d_out;                    // [N, 2] f32

    const int TB = 256;
    const int gN = (N_NODES + TB - 1) / TB;
    const int gE = (N_EDGES + TB - 1) / TB;

    k_init_deg<<<gN, TB>>>();
    k_degree  <<<gE, TB>>>(ei);
    k_node1   <<<gN, TB>>>(x, W1);
    k_edge1   <<<gE, TB>>>(ei);
    k_node2   <<<gN, TB>>>(b1, W2, out);
    k_edge2   <<<gE, TB>>>(ei, out);
    k_fin     <<<gN, TB>>>(b2, out);
}

// round 7
// speedup vs baseline: 1.2526x; 1.2526x over previous
#include <cuda_runtime.h>
#include <cstdint>

// Problem constants (from reference_code)
#define N_NODES 500000
#define N_EDGES 8000000

// ---------------- scratch (device globals: allocation-free) ----------------
// Layer-1 aggregation happens in 3-dim input space (linearity of x@W1):
//   out1[d] = dinv[d] * (sum_s xs[s] + xs[d]) @ W1 + b1,  xs = x * dinv
__device__ __align__(16) float4 g_xs  [N_NODES];   // (x*dinv, pad) 8 MB, L2-resident
__device__ __align__(16) float4 g_acc [N_NODES];   // layer-1 scatter accumulator, 8 MB
__device__ __align__(8)  float  g_hs2 [N_NODES*2]; // layer-2 scaled features, 4 MB
__device__               float  g_deg [N_NODES];   // degree (incl. self-loop)
__device__               float  g_dinv[N_NODES];   // rsqrt(deg)

// ---------------- kernels ----------------

__global__ void k_init_deg() {
    int i = blockIdx.x * blockDim.x + threadIdx.x;
    if (i < N_NODES) g_deg[i] = 1.0f;   // self-loop contributes 1
}

// 4 edges per thread, int4 index loads
__global__ void k_degree(const int* __restrict__ ei) {
    int i = blockIdx.x * blockDim.x + threadIdx.x;
    if (i >= N_EDGES / 4) return;
    int4 d4 = __ldg(reinterpret_cast<const int4*>(ei + N_EDGES) + i);
    atomicAdd(&g_deg[d4.x], 1.0f);
    atomicAdd(&g_deg[d4.y], 1.0f);
    atomicAdd(&g_deg[d4.z], 1.0f);
    atomicAdd(&g_deg[d4.w], 1.0f);
}

// dinv = rsqrt(deg); xs = x * dinv (3-vec in float4); acc = 0
__global__ void k_node1(const float* __restrict__ x) {
    int i = blockIdx.x * blockDim.x + threadIdx.x;
    if (i >= N_NODES) return;
    float dv = rsqrtf(g_deg[i]);
    g_dinv[i] = dv;
    float x0 = x[3 * i], x1 = x[3 * i + 1], x2 = x[3 * i + 2];
    g_xs [i] = make_float4(x0 * dv, x1 * dv, x2 * dv, 0.f);
    g_acc[i] = make_float4(0.f, 0.f, 0.f, 0.f);
}

// acc[dst] += xs[src]   (one 16B gather + one red.global.add.v4.f32 per edge)
__global__ void k_edge1(const int* __restrict__ ei) {
    int i = blockIdx.x * blockDim.x + threadIdx.x;
    if (i >= N_EDGES / 4) return;
    int4 s4 = __ldg(reinterpret_cast<const int4*>(ei) + i);
    int4 d4 = __ldg(reinterpret_cast<const int4*>(ei + N_EDGES) + i);
    float4 v0 = __ldg(&g_xs[s4.x]);
    float4 v1 = __ldg(&g_xs[s4.y]);
    float4 v2 = __ldg(&g_xs[s4.z]);
    float4 v3 = __ldg(&g_xs[s4.w]);
    asm volatile("red.global.add.v4.f32 [%0], {%1,%2,%3,%4};"
                 :: "l"(&g_acc[d4.x]), "f"(v0.x), "f"(v0.y), "f"(v0.z), "f"(v0.w) : "memory");
    asm volatile("red.global.add.v4.f32 [%0], {%1,%2,%3,%4};"
                 :: "l"(&g_acc[d4.y]), "f"(v1.x), "f"(v1.y), "f"(v1.z), "f"(v1.w) : "memory");
    asm volatile("red.global.add.v4.f32 [%0], {%1,%2,%3,%4};"
                 :: "l"(&g_acc[d4.z]), "f"(v2.x), "f"(v2.y), "f"(v2.z), "f"(v2.w) : "memory");
    asm volatile("red.global.add.v4.f32 [%0], {%1,%2,%3,%4};"
                 :: "l"(&g_acc[d4.w]), "f"(v3.x), "f"(v3.y), "f"(v3.z), "f"(v3.w) : "memory");
}

// t = dinv*(acc + xs)  (3-vec);  a = relu(t @ W1 + b1);  hs2 = (a @ W2) * dinv;  out = 0
__global__ void k_node2(const float* __restrict__ W1, const float* __restrict__ b1,
                        const float* __restrict__ W2, float* __restrict__ out) {
    int i = blockIdx.x * blockDim.x + threadIdx.x;
    if (i >= N_NODES) return;
    float dv = g_dinv[i];
    float4 xs = g_xs[i];
    float4 ac = g_acc[i];
    float t0 = dv * (ac.x + xs.x);
    float t1 = dv * (ac.y + xs.y);
    float t2 = dv * (ac.z + xs.z);
    float a[8];
#pragma unroll
    for (int j = 0; j < 8; j++) {
        float v = t0 * __ldg(&W1[j]) + t1 * __ldg(&W1[8 + j]) + t2 * __ldg(&W1[16 + j])
                  + __ldg(&b1[j]);
        a[j] = fmaxf(v, 0.0f);
    }
    float o0 = 0.f, o1 = 0.f;
#pragma unroll
    for (int j = 0; j < 8; j++) {
        o0 += a[j] * __ldg(&W2[2 * j]);
        o1 += a[j] * __ldg(&W2[2 * j + 1]);
    }
    reinterpret_cast<float2*>(&g_hs2[(size_t)i * 2])[0] = make_float2(o0 * dv, o1 * dv);
    reinterpret_cast<float2*>(&out[(size_t)i * 2])[0]   = make_float2(0.f, 0.f);
}

// out[dst] += hs2[src]   (one 8B gather + one red.global.add.v2.f32 per edge)
__global__ void k_edge2(const int* __restrict__ ei, float* __restrict__ out) {
    int i = blockIdx.x * blockDim.x + threadIdx.x;
    if (i >= N_EDGES / 4) return;
    int4 s4 = __ldg(reinterpret_cast<const int4*>(ei) + i);
    int4 d4 = __ldg(reinterpret_cast<const int4*>(ei + N_EDGES) + i);
    const float2* hs = reinterpret_cast<const float2*>(g_hs2);
    float2 v0 = __ldg(hs + s4.x);
    float2 v1 = __ldg(hs + s4.y);
    float2 v2 = __ldg(hs + s4.z);
    float2 v3 = __ldg(hs + s4.w);
    asm volatile("red.global.add.v2.f32 [%0], {%1,%2};"
                 :: "l"(out + (size_t)d4.x * 2), "f"(v0.x), "f"(v0.y) : "memory");
    asm volatile("red.global.add.v2.f32 [%0], {%1,%2};"
                 :: "l"(out + (size_t)d4.y * 2), "f"(v1.x), "f"(v1.y) : "memory");
    asm volatile("red.global.add.v2.f32 [%0], {%1,%2};"
                 :: "l"(out + (size_t)d4.z * 2), "f"(v2.x), "f"(v2.y) : "memory");
    asm volatile("red.global.add.v2.f32 [%0], {%1,%2};"
                 :: "l"(out + (size_t)d4.w * 2), "f"(v3.x), "f"(v3.y) : "memory");
}

// out = dinv*(out + hs2) + b2
__global__ void k_fin(const float* __restrict__ b2, float* __restrict__ out) {
    int i = blockIdx.x * blockDim.x + threadIdx.x;
    if (i >= N_NODES) return;
    float dv = g_dinv[i];
    float2* op = reinterpret_cast<float2*>(&out[(size_t)i * 2]);
    float2 acc = op[0];
    const float2 h = reinterpret_cast<const float2*>(&g_hs2[(size_t)i * 2])[0];
    op[0] = make_float2(dv * (acc.x + h.x) + __ldg(&b2[0]),
                        dv * (acc.y + h.y) + __ldg(&b2[1]));
}

// ---------------- launch ----------------
extern "C" void kernel_launch(void* const* d_in, const int* in_sizes, int n_in,
                              void* d_out, int out_size) {
    const float* x  = (const float*)d_in[0];       // [N, 3] f32
    const int*   ei = (const int*)d_in[1];         // [2, E] int32
    // d_in[2] = W1 [3,8], d_in[3] = b1 [8], d_in[4] = W2 [8,2], d_in[5] = b2 [2]
    const float* W1 = (const float*)d_in[2];
    const float* b1 = (const float*)d_in[3];
    const float* W2 = (const float*)d_in[4];
    const float* b2 = (const float*)d_in[5];
    float* out = (float*)d_out;                    // [N, 2] f32

    const int TB = 256;
    const int gN  = (N_NODES + TB - 1) / TB;
    const int gE4 = (N_EDGES / 4 + TB - 1) / TB;

    k_init_deg<<<gN, TB>>>();
    k_degree  <<<gE4, TB>>>(ei);
    k_node1   <<<gN, TB>>>(x);
    k_edge1   <<<gE4, TB>>>(ei);
    k_node2   <<<gN, TB>>>(W1, b1, W2, out);
    k_edge2   <<<gE4, TB>>>(ei, out);
    k_fin     <<<gN, TB>>>(b2, out);
}